// round 3
// baseline (speedup 1.0000x reference)
#include <cuda_runtime.h>
#include <math.h>

#define BATCH 2
#define TLEN  1024
#define NH    8
#define HDIM  64
#define HID   512
#define KDIM  512
#define BT    (BATCH*TLEN)

// ---------------- scratch ----------------
__device__ float g_xq[BT*KDIM];
__device__ float g_xk[BT*KDIM];
__device__ float g_xv[BT*KDIM];
__device__ float g_q [BT*KDIM];
__device__ float g_k [BT*KDIM];
__device__ float g_v [BT*KDIM];
__device__ float g_g [BT*KDIM];
__device__ float g_oc[BT*KDIM];
__device__ float g_act[BT*KDIM];
__device__ float g_beta [BT*NH];
__device__ float g_alpha[BT*NH];
__device__ float g_cos[TLEN*32];
__device__ float g_sin[TLEN*32];

// ---------------- helpers ----------------
__device__ __forceinline__ void fma2(unsigned long long& d,
                                     unsigned long long a,
                                     unsigned long long b)
{
    asm("fma.rn.f32x2 %0, %1, %2, %0;" : "+l"(d) : "l"(a), "l"(b));
}

__device__ __forceinline__ float red32(float x)
{
#pragma unroll
    for (int m = 16; m; m >>= 1) x += __shfl_xor_sync(0xffffffffu, x, m);
    return x;
}

__device__ __forceinline__ float red16(float x)
{
    x += __shfl_xor_sync(0xffffffffu, x, 8);
    x += __shfl_xor_sync(0xffffffffu, x, 4);
    x += __shfl_xor_sync(0xffffffffu, x, 2);
    x += __shfl_xor_sync(0xffffffffu, x, 1);
    return x;
}

// ---------------- GEMM: C[2048,512] = A[2048,512] @ B[512,512]^T --------------
// FFMA2 microkernel: thread tile = 4 m-pairs x 4 n. B duplicated in smem so the
// n-operand is a ready-made {b,b} pair (no per-iteration MOV duplication).
__device__ __forceinline__ void gemm_body(const float* __restrict__ A,
                                          const float* __restrict__ Bw,
                                          float* __restrict__ C)
{
    __shared__ __align__(16) float As[16][132];
    __shared__ __align__(16) float Bsd[16][136];   // 64 n-values duplicated -> 128 + pad
    const int tid = threadIdx.x;
    const int tx = tid & 15, ty = tid >> 4;
    const int m0 = blockIdx.y * 128, n0 = blockIdx.x * 64;

    unsigned long long acc[4][4];
#pragma unroll
    for (int p = 0; p < 4; p++)
#pragma unroll
        for (int j = 0; j < 4; j++) acc[p][j] = 0ull;

    for (int kt = 0; kt < 512; kt += 16) {
        // load A tile (transposed into As[k][m])
#pragma unroll
        for (int i = 0; i < 2; i++) {
            int idx = tid + i * 256;
            int row = idx >> 2, kq = (idx & 3) << 2;
            float4 va = *(const float4*)(A + (size_t)(m0 + row) * 512 + kt + kq);
            As[kq + 0][row] = va.x; As[kq + 1][row] = va.y;
            As[kq + 2][row] = va.z; As[kq + 3][row] = va.w;
        }
        // load B tile, duplicated: Bsd[k][2n] = Bsd[k][2n+1] = B[n][k]
        {
            int row = tid >> 2, kq = (tid & 3) << 2;
            float4 vb = *(const float4*)(Bw + (size_t)(n0 + row) * 512 + kt + kq);
            *(float2*)&Bsd[kq + 0][row * 2] = make_float2(vb.x, vb.x);
            *(float2*)&Bsd[kq + 1][row * 2] = make_float2(vb.y, vb.y);
            *(float2*)&Bsd[kq + 2][row * 2] = make_float2(vb.z, vb.z);
            *(float2*)&Bsd[kq + 3][row * 2] = make_float2(vb.w, vb.w);
        }
        __syncthreads();
#pragma unroll
        for (int kk = 0; kk < 16; kk++) {
            ulonglong2 a01 = *(const ulonglong2*)&As[kk][ty * 8];
            ulonglong2 a23 = *(const ulonglong2*)&As[kk][ty * 8 + 4];
            ulonglong2 b01 = *(const ulonglong2*)&Bsd[kk][tx * 8];
            ulonglong2 b23 = *(const ulonglong2*)&Bsd[kk][tx * 8 + 4];
            unsigned long long ap[4] = {a01.x, a01.y, a23.x, a23.y};
            unsigned long long bp[4] = {b01.x, b01.y, b23.x, b23.y};
#pragma unroll
            for (int p = 0; p < 4; p++)
#pragma unroll
                for (int j = 0; j < 4; j++)
                    fma2(acc[p][j], ap[p], bp[j]);
        }
        __syncthreads();
    }
#pragma unroll
    for (int p = 0; p < 4; p++) {
        float2 a0 = *(float2*)&acc[p][0];
        float2 a1 = *(float2*)&acc[p][1];
        float2 a2 = *(float2*)&acc[p][2];
        float2 a3 = *(float2*)&acc[p][3];
        int m = m0 + ty * 8 + 2 * p;
        *(float4*)(C + (size_t)m * 512 + n0 + tx * 4) =
            make_float4(a0.x, a1.x, a2.x, a3.x);
        *(float4*)(C + (size_t)(m + 1) * 512 + n0 + tx * 4) =
            make_float4(a0.y, a1.y, a2.y, a3.y);
    }
}

__global__ __launch_bounds__(256) void gemm_qkvg(const float* __restrict__ x,
    const float* __restrict__ Wq, const float* __restrict__ Wk,
    const float* __restrict__ Wv, const float* __restrict__ Wg)
{
    const float* Bw; float* C;
    switch (blockIdx.z) {
        case 0:  Bw = Wq; C = g_xq; break;
        case 1:  Bw = Wk; C = g_xk; break;
        case 2:  Bw = Wv; C = g_xv; break;
        default: Bw = Wg; C = g_g;  break;
    }
    gemm_body(x, Bw, C);
}

__global__ __launch_bounds__(256) void gemm_out(const float* __restrict__ Wo,
                                                float* __restrict__ out)
{
    gemm_body(g_act, Wo, out);
}

// ---------------- beta / alpha small projection -------------------------------
__global__ __launch_bounds__(128) void small_proj(const float* __restrict__ x,
    const float* __restrict__ Wb, const float* __restrict__ bb,
    const float* __restrict__ Wgk, const float* __restrict__ bgk,
    const float* __restrict__ A_log, const float* __restrict__ dtb)
{
    __shared__ float xs[512];
    const int bt = blockIdx.x;
    const int tid = threadIdx.x;
    for (int i = tid; i < 512; i += 128) xs[i] = x[(size_t)bt * 512 + i];
    __syncthreads();
    const int warp = tid >> 5, lane = tid & 31;
#pragma unroll
    for (int oi = 0; oi < 4; oi++) {
        int out = warp * 4 + oi;
        const float* w = (out < 8) ? (Wb + out * 512) : (Wgk + (out - 8) * 512);
        float s = 0.0f;
#pragma unroll
        for (int i = 0; i < 16; i++) s = fmaf(xs[lane + i * 32], w[lane + i * 32], s);
        s = red32(s);
        if (lane == 0) {
            if (out < 8) {
                float z = s + bb[out];
                g_beta[bt * 8 + out] = 1.0f / (1.0f + expf(-z));
            } else {
                int h = out - 8;
                float z = s + bgk[h] + dtb[h];
                float sp = (z > 20.0f) ? z : log1pf(expf(z));
                g_alpha[bt * 8 + h] = expf(-expf(A_log[h]) * sp);
            }
        }
    }
}

// ---------------- depthwise causal conv (width 4) + silu ----------------------
__global__ __launch_bounds__(128) void conv_silu(
    const float* __restrict__ cqw, const float* __restrict__ cqb,
    const float* __restrict__ ckw, const float* __restrict__ ckb,
    const float* __restrict__ cvw, const float* __restrict__ cvb)
{
    const float *xin, *w, *bi; float* out;
    switch (blockIdx.y) {
        case 0:  xin = g_xq; w = cqw; bi = cqb; out = g_q; break;
        case 1:  xin = g_xk; w = ckw; bi = ckb; out = g_k; break;
        default: xin = g_xv; w = cvw; bi = cvb; out = g_v; break;
    }
    const int c = threadIdx.x * 4;
    const int t0 = blockIdx.x * 32;
    const int b  = blockIdx.z;

    float4 wr0 = *(const float4*)(w + (c + 0) * 4);
    float4 wr1 = *(const float4*)(w + (c + 1) * 4);
    float4 wr2 = *(const float4*)(w + (c + 2) * 4);
    float4 wr3 = *(const float4*)(w + (c + 3) * 4);
    float4 bias = *(const float4*)(bi + c);

    const float* xrow = xin + (size_t)b * TLEN * 512 + c;
    float*       orow = out + (size_t)b * TLEN * 512 + c;
    const float4 zero = make_float4(0.f, 0.f, 0.f, 0.f);

    float4 h0 = (t0 - 3 >= 0) ? *(const float4*)(xrow + (size_t)(t0 - 3) * 512) : zero;
    float4 h1 = (t0 - 2 >= 0) ? *(const float4*)(xrow + (size_t)(t0 - 2) * 512) : zero;
    float4 h2 = (t0 - 1 >= 0) ? *(const float4*)(xrow + (size_t)(t0 - 1) * 512) : zero;
    float4 cur = *(const float4*)(xrow + (size_t)t0 * 512);

    for (int t = t0; t < t0 + 32; t++) {
        float4 nxt = (t + 1 < TLEN) ? *(const float4*)(xrow + (size_t)(t + 1) * 512) : zero;
        float4 acc = bias;
        acc.x = fmaf(h0.x, wr0.x, acc.x); acc.x = fmaf(h1.x, wr0.y, acc.x);
        acc.x = fmaf(h2.x, wr0.z, acc.x); acc.x = fmaf(cur.x, wr0.w, acc.x);
        acc.y = fmaf(h0.y, wr1.x, acc.y); acc.y = fmaf(h1.y, wr1.y, acc.y);
        acc.y = fmaf(h2.y, wr1.z, acc.y); acc.y = fmaf(cur.y, wr1.w, acc.y);
        acc.z = fmaf(h0.z, wr2.x, acc.z); acc.z = fmaf(h1.z, wr2.y, acc.z);
        acc.z = fmaf(h2.z, wr2.z, acc.z); acc.z = fmaf(cur.z, wr2.w, acc.z);
        acc.w = fmaf(h0.w, wr3.x, acc.w); acc.w = fmaf(h1.w, wr3.y, acc.w);
        acc.w = fmaf(h2.w, wr3.z, acc.w); acc.w = fmaf(cur.w, wr3.w, acc.w);
        float4 o;
        o.x = acc.x / (1.0f + expf(-acc.x));
        o.y = acc.y / (1.0f + expf(-acc.y));
        o.z = acc.z / (1.0f + expf(-acc.z));
        o.w = acc.w / (1.0f + expf(-acc.w));
        *(float4*)(orow + (size_t)t * 512) = o;
        h0 = h1; h1 = h2; h2 = cur; cur = nxt;
    }
}

// ---------------- RoPE tables (fp64, recomputed every launch) -----------------
__global__ void rope_init()
{
    int idx = blockIdx.x * blockDim.x + threadIdx.x;
    if (idx >= TLEN * 32) return;
    int t = idx >> 5, j = idx & 31;
    const double PI = 3.14159265358979323846;
    double ar = (double)j / 32.0;
    double sbase = 10000.0 * pow(32.0, 64.0 / 62.0);
    double inv_freq = pow(sbase, -ar);
    double freq_extra = pow(10000.0, -ar);
    double wavelen = (2.0 * PI) / freq_extra;
    double ramp = (wavelen - 1.0) / 31.0;
    ramp = ramp < 0.0 ? 0.0 : (ramp > 1.0 ? 1.0 : ramp);
    double spf = 1.0 + 31.0 * ramp;
    double f = (double)t / spf * inv_freq;
    g_cos[idx] = (float)cos(f);
    g_sin[idx] = (float)sin(f);
}

// ---------------- RoPE + l2norm, in-place on g_q / g_k ------------------------
__global__ __launch_bounds__(256) void rope_l2norm()
{
    int gw = (blockIdx.x * blockDim.x + threadIdx.x) >> 5;
    int lane = threadIdx.x & 31;
    if (gw >= BT * NH) return;
    int t = (gw >> 3) & 1023;
    int j = (2 * lane) & 31;
    float c = g_cos[t * 32 + j], s = g_sin[t * 32 + j];
    size_t base = (size_t)gw * 64;
#pragma unroll
    for (int which = 0; which < 2; which++) {
        float* p = which ? g_k : g_q;
        float x1 = p[base + 2 * lane];
        float x2 = p[base + 2 * lane + 1];
        float o1 = x1 * c - x2 * s;
        float o2 = x1 * s + x2 * c;
        float ss = red32(o1 * o1 + o2 * o2);
        float inv = 1.0f / fmaxf(sqrtf(ss), 1e-12f);
        // shfl chain synchronizes the warp: all loads complete before stores
        p[base + lane]      = o1 * inv;
        p[base + 32 + lane] = o2 * inv;
    }
}

// ---------------- delta-rule scan ---------------------------------------------
// grid (16, 4): (b*h, e-group). 256 threads: tid = el*16 + r.
// Lane owns S[d0..d0+3][e], e = eg*16+el, d0 = r*4. 16-lane shfl reductions.
__global__ __launch_bounds__(256) void scan_kernel()
{
    const int bh = blockIdx.x;           // 0..15
    const int eg = blockIdx.y;           // 0..3
    const int b = bh >> 3, h = bh & 7;
    const int tid = threadIdx.x;
    const int el = tid >> 4, r = tid & 15;
    const int e  = eg * 16 + el;
    const int d0 = r * 4;

    const size_t head = ((size_t)b * TLEN * NH + h) * 64;
    const float* qp = g_q + head;
    const float* kp = g_k + head;
    const float* vp = g_v + head;
    float*       op = g_oc + head;
    const float* ap = g_alpha + (size_t)b * TLEN * NH + h;
    const float* bp = g_beta  + (size_t)b * TLEN * NH + h;

    float4 S = make_float4(0.f, 0.f, 0.f, 0.f);

    float4 kc = *(const float4*)(kp + d0);
    float4 qc = *(const float4*)(qp + d0);
    float  vc = vp[e];
    float  ac = ap[0];
    float  bc = bp[0];

    for (int t = 0; t < TLEN; t++) {
        float4 kn = make_float4(0.f,0.f,0.f,0.f), qn = kn;
        float  vn = 0.f, an = 0.f, bn = 0.f;
        if (t + 1 < TLEN) {
            size_t off = (size_t)(t + 1) * 512;
            kn = *(const float4*)(kp + off + d0);
            qn = *(const float4*)(qp + off + d0);
            vn = vp[off + e];
            an = ap[(size_t)(t + 1) * 8];
            bn = bp[(size_t)(t + 1) * 8];
        }
        float ks = kc.x * S.x + kc.y * S.y + kc.z * S.z + kc.w * S.w;
        ks = red16(ks);
        float c1 = bc * fmaf(-ac, ks, vc);
        S.x = fmaf(kc.x, c1, ac * S.x);
        S.y = fmaf(kc.y, c1, ac * S.y);
        S.z = fmaf(kc.z, c1, ac * S.z);
        S.w = fmaf(kc.w, c1, ac * S.w);
        float os = qc.x * S.x + qc.y * S.y + qc.z * S.z + qc.w * S.w;
        os = red16(os);
        if (r == 0) op[(size_t)t * 512 + e] = os;
        kc = kn; qc = qn; vc = vn; ac = an; bc = bn;
    }
}

// ---------------- post: +D*v, RMS norm, gate ----------------------------------
__global__ __launch_bounds__(256) void postproc(const float* __restrict__ D,
                                                const float* __restrict__ onw)
{
    int gw = (blockIdx.x * blockDim.x + threadIdx.x) >> 5;
    int lane = threadIdx.x & 31;
    if (gw >= BT * NH) return;
    int h = gw & 7;
    size_t base = (size_t)gw * 64;
    float d = D[h];
    float o1 = g_oc[base + lane]      + d * g_v[base + lane];
    float o2 = g_oc[base + 32 + lane] + d * g_v[base + 32 + lane];
    float ss = red32(o1 * o1 + o2 * o2);
    float sc = rsqrtf(ss * (1.0f / 64.0f) + 1e-6f);
    float on1 = o1 * sc * onw[lane];
    float on2 = o2 * sc * onw[32 + lane];
    float g1 = g_g[base + lane], g2 = g_g[base + 32 + lane];
    g_act[base + lane]      = g1 * (on1 / (1.0f + expf(-on1)));
    g_act[base + 32 + lane] = g2 * (on2 / (1.0f + expf(-on2)));
}

// ---------------- launch ------------------------------------------------------
extern "C" void kernel_launch(void* const* d_in, const int* in_sizes, int n_in,
                              void* d_out, int out_size)
{
    const float* x    = (const float*)d_in[0];
    const float* Wq   = (const float*)d_in[1];
    const float* Wk   = (const float*)d_in[2];
    const float* Wv   = (const float*)d_in[3];
    const float* Wg   = (const float*)d_in[4];
    const float* Wo   = (const float*)d_in[5];
    const float* Wb   = (const float*)d_in[6];
    const float* bb   = (const float*)d_in[7];
    const float* Wgk  = (const float*)d_in[8];
    const float* bgk  = (const float*)d_in[9];
    const float* cqw  = (const float*)d_in[10];
    const float* cqb  = (const float*)d_in[11];
    const float* ckw  = (const float*)d_in[12];
    const float* ckb  = (const float*)d_in[13];
    const float* cvw  = (const float*)d_in[14];
    const float* cvb  = (const float*)d_in[15];
    const float* A_log= (const float*)d_in[16];
    const float* D    = (const float*)d_in[17];
    const float* dtb  = (const float*)d_in[18];
    const float* onw  = (const float*)d_in[19];
    float* out = (float*)d_out;

    rope_init<<<(TLEN * 32 + 255) / 256, 256>>>();
    gemm_qkvg<<<dim3(8, 16, 4), 256>>>(x, Wq, Wk, Wv, Wg);
    small_proj<<<BT, 128>>>(x, Wb, bb, Wgk, bgk, A_log, dtb);
    conv_silu<<<dim3(32, 3, 2), 128>>>(cqw, cqb, ckw, ckb, cvw, cvb);
    rope_l2norm<<<2048, 256>>>();
    scan_kernel<<<dim3(16, 4), 256>>>();
    postproc<<<2048, 256>>>(D, onw);
    gemm_out<<<dim3(8, 16, 1), 256>>>(Wo, out);
}

// round 6
// speedup vs baseline: 1.2811x; 1.2811x over previous
#include <cuda_runtime.h>
#include <cstdint>
#include <math.h>

#define BATCH 2
#define TLEN  1024
#define NH    8
#define HDIM  64
#define HID   512
#define KDIM  512
#define BT    (BATCH*TLEN)

// ---------------- scratch ----------------
__device__ float g_xq[BT*KDIM];
__device__ float g_xk[BT*KDIM];
__device__ float g_xv[BT*KDIM];
__device__ float g_q [BT*KDIM];
__device__ float g_k [BT*KDIM];
__device__ float g_v [BT*KDIM];
__device__ float g_g [BT*KDIM];
__device__ float g_oc[BT*KDIM];
__device__ float g_act[BT*KDIM];
__device__ float g_beta [BT*NH];
__device__ float g_alpha[BT*NH];
__device__ float g_cos[TLEN*32];
__device__ float g_sin[TLEN*32];

// ---------------- helpers ----------------
__device__ __forceinline__ float red32(float x)
{
#pragma unroll
    for (int m = 16; m; m >>= 1) x += __shfl_xor_sync(0xffffffffu, x, m);
    return x;
}
__device__ __forceinline__ float red16(float x)
{
    x += __shfl_xor_sync(0xffffffffu, x, 8);
    x += __shfl_xor_sync(0xffffffffu, x, 4);
    x += __shfl_xor_sync(0xffffffffu, x, 2);
    x += __shfl_xor_sync(0xffffffffu, x, 1);
    return x;
}

// ---------------- GEMM: C[2048,512] = A[2048,512] @ B[512,512]^T --------------
// Software-pipelined: register prefetch of next k-tile + ping-pong smem buffers,
// single __syncthreads per k-step. Thread tile 8x4, block tile 128x64.
__device__ __forceinline__ void gemm_body(const float* __restrict__ A,
                                          const float* __restrict__ Bw,
                                          float* __restrict__ C)
{
    __shared__ __align__(16) float As[2][16][132];
    __shared__ __align__(16) float Bs[2][16][68];
    const int tid = threadIdx.x;
    const int tx = tid & 15, ty = tid >> 4;
    const int m0 = blockIdx.y * 128, n0 = blockIdx.x * 64;

    // per-thread load coordinates
    const int arow0 = (tid)       >> 2, akq0 = ((tid)       & 3) << 2;
    const int arow1 = (tid + 256) >> 2, akq1 = ((tid + 256) & 3) << 2;
    const int brow  = tid >> 2,         bkq  = (tid & 3) << 2;

    const float* aptr0 = A  + (size_t)(m0 + arow0) * 512 + akq0;
    const float* aptr1 = A  + (size_t)(m0 + arow1) * 512 + akq1;
    const float* bptr  = Bw + (size_t)(n0 + brow)  * 512 + bkq;

    float acc[8][4];
#pragma unroll
    for (int i = 0; i < 8; i++)
#pragma unroll
        for (int j = 0; j < 4; j++) acc[i][j] = 0.0f;

    // prologue: load kt=0 into registers, store to buffer 0
    float4 va0 = *(const float4*)(aptr0);
    float4 va1 = *(const float4*)(aptr1);
    float4 vb  = *(const float4*)(bptr);
    {
        As[0][akq0 + 0][arow0] = va0.x; As[0][akq0 + 1][arow0] = va0.y;
        As[0][akq0 + 2][arow0] = va0.z; As[0][akq0 + 3][arow0] = va0.w;
        As[0][akq1 + 0][arow1] = va1.x; As[0][akq1 + 1][arow1] = va1.y;
        As[0][akq1 + 2][arow1] = va1.z; As[0][akq1 + 3][arow1] = va1.w;
        Bs[0][bkq + 0][brow] = vb.x; Bs[0][bkq + 1][brow] = vb.y;
        Bs[0][bkq + 2][brow] = vb.z; Bs[0][bkq + 3][brow] = vb.w;
    }
    __syncthreads();

    for (int kt = 0; kt < 32; kt++) {
        const int cur = kt & 1;
        // prefetch next tile into registers (in flight during compute)
        if (kt + 1 < 32) {
            int ko = (kt + 1) * 16;
            va0 = *(const float4*)(aptr0 + ko);
            va1 = *(const float4*)(aptr1 + ko);
            vb  = *(const float4*)(bptr  + ko);
        }
#pragma unroll
        for (int kk = 0; kk < 16; kk++) {
            float4 a0 = *(const float4*)&As[cur][kk][ty * 8];
            float4 a1 = *(const float4*)&As[cur][kk][ty * 8 + 4];
            float4 b0 = *(const float4*)&Bs[cur][kk][tx * 4];
            float av[8] = {a0.x, a0.y, a0.z, a0.w, a1.x, a1.y, a1.z, a1.w};
            float bv[4] = {b0.x, b0.y, b0.z, b0.w};
#pragma unroll
            for (int i = 0; i < 8; i++)
#pragma unroll
                for (int j = 0; j < 4; j++)
                    acc[i][j] = fmaf(av[i], bv[j], acc[i][j]);
        }
        // store prefetched regs into the other buffer, then one sync
        if (kt + 1 < 32) {
            const int nxt = cur ^ 1;
            As[nxt][akq0 + 0][arow0] = va0.x; As[nxt][akq0 + 1][arow0] = va0.y;
            As[nxt][akq0 + 2][arow0] = va0.z; As[nxt][akq0 + 3][arow0] = va0.w;
            As[nxt][akq1 + 0][arow1] = va1.x; As[nxt][akq1 + 1][arow1] = va1.y;
            As[nxt][akq1 + 2][arow1] = va1.z; As[nxt][akq1 + 3][arow1] = va1.w;
            Bs[nxt][bkq + 0][brow] = vb.x; Bs[nxt][bkq + 1][brow] = vb.y;
            Bs[nxt][bkq + 2][brow] = vb.z; Bs[nxt][bkq + 3][brow] = vb.w;
            __syncthreads();
        }
    }
#pragma unroll
    for (int i = 0; i < 8; i++) {
        float4 o = make_float4(acc[i][0], acc[i][1], acc[i][2], acc[i][3]);
        *(float4*)(C + (size_t)(m0 + ty * 8 + i) * 512 + n0 + tx * 4) = o;
    }
}

__global__ __launch_bounds__(256) void gemm_qkvg(const float* __restrict__ x,
    const float* __restrict__ Wq, const float* __restrict__ Wk,
    const float* __restrict__ Wv, const float* __restrict__ Wg)
{
    const float* Bw; float* C;
    switch (blockIdx.z) {
        case 0:  Bw = Wq; C = g_xq; break;
        case 1:  Bw = Wk; C = g_xk; break;
        case 2:  Bw = Wv; C = g_xv; break;
        default: Bw = Wg; C = g_g;  break;
    }
    gemm_body(x, Bw, C);
}

__global__ __launch_bounds__(256) void gemm_out(const float* __restrict__ Wo,
                                                float* __restrict__ out)
{
    gemm_body(g_act, Wo, out);
}

// ---------------- beta / alpha small projection -------------------------------
__global__ __launch_bounds__(128) void small_proj(const float* __restrict__ x,
    const float* __restrict__ Wb, const float* __restrict__ bb,
    const float* __restrict__ Wgk, const float* __restrict__ bgk,
    const float* __restrict__ A_log, const float* __restrict__ dtb)
{
    __shared__ float xs[512];
    const int bt = blockIdx.x;
    const int tid = threadIdx.x;
    for (int i = tid; i < 512; i += 128) xs[i] = x[(size_t)bt * 512 + i];
    __syncthreads();
    const int warp = tid >> 5, lane = tid & 31;
#pragma unroll
    for (int oi = 0; oi < 4; oi++) {
        int out = warp * 4 + oi;
        const float* w = (out < 8) ? (Wb + out * 512) : (Wgk + (out - 8) * 512);
        float s = 0.0f;
#pragma unroll
        for (int i = 0; i < 16; i++) s = fmaf(xs[lane + i * 32], w[lane + i * 32], s);
        s = red32(s);
        if (lane == 0) {
            if (out < 8) {
                float z = s + bb[out];
                g_beta[bt * 8 + out] = 1.0f / (1.0f + expf(-z));
            } else {
                int h = out - 8;
                float z = s + bgk[h] + dtb[h];
                float sp = (z > 20.0f) ? z : log1pf(expf(z));
                g_alpha[bt * 8 + h] = expf(-expf(A_log[h]) * sp);
            }
        }
    }
}

// ---------------- depthwise causal conv (width 4) + silu ----------------------
// Thread owns 4 channels x 8 timesteps; sliding window in registers.
__global__ __launch_bounds__(128) void conv_silu(
    const float* __restrict__ cqw, const float* __restrict__ cqb,
    const float* __restrict__ ckw, const float* __restrict__ ckb,
    const float* __restrict__ cvw, const float* __restrict__ cvb)
{
    const float *xin, *w, *bi; float* out;
    switch (blockIdx.y) {
        case 0:  xin = g_xq; w = cqw; bi = cqb; out = g_q; break;
        case 1:  xin = g_xk; w = ckw; bi = ckb; out = g_k; break;
        default: xin = g_xv; w = cvw; bi = cvb; out = g_v; break;
    }
    const int c = threadIdx.x * 4;
    const int t0 = blockIdx.x * 8;
    const int b  = blockIdx.z;

    float4 wr0 = *(const float4*)(w + (c + 0) * 4);
    float4 wr1 = *(const float4*)(w + (c + 1) * 4);
    float4 wr2 = *(const float4*)(w + (c + 2) * 4);
    float4 wr3 = *(const float4*)(w + (c + 3) * 4);
    float4 bias = *(const float4*)(bi + c);

    const float* xrow = xin + (size_t)b * TLEN * 512 + c;
    float*       orow = out + (size_t)b * TLEN * 512 + c;
    const float4 zero = make_float4(0.f, 0.f, 0.f, 0.f);

    float4 h0 = (t0 - 3 >= 0) ? *(const float4*)(xrow + (size_t)(t0 - 3) * 512) : zero;
    float4 h1 = (t0 - 2 >= 0) ? *(const float4*)(xrow + (size_t)(t0 - 2) * 512) : zero;
    float4 h2 = (t0 - 1 >= 0) ? *(const float4*)(xrow + (size_t)(t0 - 1) * 512) : zero;
    float4 cur = *(const float4*)(xrow + (size_t)t0 * 512);

#pragma unroll
    for (int t = t0; t < t0 + 8; t++) {
        float4 nxt = (t + 1 < TLEN) ? *(const float4*)(xrow + (size_t)(t + 1) * 512) : zero;
        float4 acc = bias;
        acc.x = fmaf(h0.x, wr0.x, acc.x); acc.x = fmaf(h1.x, wr0.y, acc.x);
        acc.x = fmaf(h2.x, wr0.z, acc.x); acc.x = fmaf(cur.x, wr0.w, acc.x);
        acc.y = fmaf(h0.y, wr1.x, acc.y); acc.y = fmaf(h1.y, wr1.y, acc.y);
        acc.y = fmaf(h2.y, wr1.z, acc.y); acc.y = fmaf(cur.y, wr1.w, acc.y);
        acc.z = fmaf(h0.z, wr2.x, acc.z); acc.z = fmaf(h1.z, wr2.y, acc.z);
        acc.z = fmaf(h2.z, wr2.z, acc.z); acc.z = fmaf(cur.z, wr2.w, acc.z);
        acc.w = fmaf(h0.w, wr3.x, acc.w); acc.w = fmaf(h1.w, wr3.y, acc.w);
        acc.w = fmaf(h2.w, wr3.z, acc.w); acc.w = fmaf(cur.w, wr3.w, acc.w);
        float4 o;
        o.x = acc.x / (1.0f + expf(-acc.x));
        o.y = acc.y / (1.0f + expf(-acc.y));
        o.z = acc.z / (1.0f + expf(-acc.z));
        o.w = acc.w / (1.0f + expf(-acc.w));
        *(float4*)(orow + (size_t)t * 512) = o;
        h0 = h1; h1 = h2; h2 = cur; cur = nxt;
    }
}

// ---------------- RoPE tables (fp64, recomputed every launch) -----------------
__global__ void rope_init()
{
    int idx = blockIdx.x * blockDim.x + threadIdx.x;
    if (idx >= TLEN * 32) return;
    int t = idx >> 5, j = idx & 31;
    const double PI = 3.14159265358979323846;
    double ar = (double)j / 32.0;
    double sbase = 10000.0 * pow(32.0, 64.0 / 62.0);
    double inv_freq = pow(sbase, -ar);
    double freq_extra = pow(10000.0, -ar);
    double wavelen = (2.0 * PI) / freq_extra;
    double ramp = (wavelen - 1.0) / 31.0;
    ramp = ramp < 0.0 ? 0.0 : (ramp > 1.0 ? 1.0 : ramp);
    double spf = 1.0 + 31.0 * ramp;
    double f = (double)t / spf * inv_freq;
    g_cos[idx] = (float)cos(f);
    g_sin[idx] = (float)sin(f);
}

// ---------------- RoPE + l2norm, in-place on g_q / g_k ------------------------
__global__ __launch_bounds__(256) void rope_l2norm()
{
    int gw = (blockIdx.x * blockDim.x + threadIdx.x) >> 5;
    int lane = threadIdx.x & 31;
    if (gw >= BT * NH) return;
    int t = (gw >> 3) & 1023;
    int j = (2 * lane) & 31;
    float c = g_cos[t * 32 + j], s = g_sin[t * 32 + j];
    size_t base = (size_t)gw * 64;
#pragma unroll
    for (int which = 0; which < 2; which++) {
        float* p = which ? g_k : g_q;
        float x1 = p[base + 2 * lane];
        float x2 = p[base + 2 * lane + 1];
        float o1 = x1 * c - x2 * s;
        float o2 = x1 * s + x2 * c;
        float ss = red32(o1 * o1 + o2 * o2);
        float inv = 1.0f / fmaxf(sqrtf(ss), 1e-12f);
        // shfl chain synchronizes the warp: all loads complete before stores
        p[base + lane]      = o1 * inv;
        p[base + 32 + lane] = o2 * inv;
    }
}

// ---------------- delta-rule scan ---------------------------------------------
// grid (16, 4): (b*h, e-group). 256 threads: tid = el*16 + r.
// Lane owns S[d0..d0+3][e], e = eg*16+el, d0 = r*4. 16-lane shfl reductions.
__global__ __launch_bounds__(256) void scan_kernel()
{
    const int bh = blockIdx.x;           // 0..15
    const int eg = blockIdx.y;           // 0..3
    const int b = bh >> 3, h = bh & 7;
    const int tid = threadIdx.x;
    const int el = tid >> 4, r = tid & 15;
    const int e  = eg * 16 + el;
    const int d0 = r * 4;

    const size_t head = ((size_t)b * TLEN * NH + h) * 64;
    const float* qp = g_q + head;
    const float* kp = g_k + head;
    const float* vp = g_v + head;
    float*       op = g_oc + head;
    const float* ap = g_alpha + (size_t)b * TLEN * NH + h;
    const float* bp = g_beta  + (size_t)b * TLEN * NH + h;

    float4 S = make_float4(0.f, 0.f, 0.f, 0.f);

    float4 kc = *(const float4*)(kp + d0);
    float4 qc = *(const float4*)(qp + d0);
    float  vc = vp[e];
    float  ac = ap[0];
    float  bc = bp[0];

    for (int t = 0; t < TLEN; t++) {
        float4 kn = make_float4(0.f,0.f,0.f,0.f), qn = kn;
        float  vn = 0.f, an = 0.f, bn = 0.f;
        if (t + 1 < TLEN) {
            size_t off = (size_t)(t + 1) * 512;
            kn = *(const float4*)(kp + off + d0);
            qn = *(const float4*)(qp + off + d0);
            vn = vp[off + e];
            an = ap[(size_t)(t + 1) * 8];
            bn = bp[(size_t)(t + 1) * 8];
        }
        float ks = kc.x * S.x + kc.y * S.y + kc.z * S.z + kc.w * S.w;
        ks = red16(ks);
        float c1 = bc * fmaf(-ac, ks, vc);
        S.x = fmaf(kc.x, c1, ac * S.x);
        S.y = fmaf(kc.y, c1, ac * S.y);
        S.z = fmaf(kc.z, c1, ac * S.z);
        S.w = fmaf(kc.w, c1, ac * S.w);
        float os = qc.x * S.x + qc.y * S.y + qc.z * S.z + qc.w * S.w;
        os = red16(os);
        if (r == 0) op[(size_t)t * 512 + e] = os;
        kc = kn; qc = qn; vc = vn; ac = an; bc = bn;
    }
}

// ---------------- post: +D*v, RMS norm, gate ----------------------------------
__global__ __launch_bounds__(256) void postproc(const float* __restrict__ D,
                                                const float* __restrict__ onw)
{
    int gw = (blockIdx.x * blockDim.x + threadIdx.x) >> 5;
    int lane = threadIdx.x & 31;
    if (gw >= BT * NH) return;
    int h = gw & 7;
    size_t base = (size_t)gw * 64;
    float d = D[h];
    float o1 = g_oc[base + lane]      + d * g_v[base + lane];
    float o2 = g_oc[base + 32 + lane] + d * g_v[base + 32 + lane];
    float ss = red32(o1 * o1 + o2 * o2);
    float sc = rsqrtf(ss * (1.0f / 64.0f) + 1e-6f);
    float on1 = o1 * sc * onw[lane];
    float on2 = o2 * sc * onw[32 + lane];
    float g1 = g_g[base + lane], g2 = g_g[base + 32 + lane];
    g_act[base + lane]      = g1 * (on1 / (1.0f + expf(-on1)));
    g_act[base + 32 + lane] = g2 * (on2 / (1.0f + expf(-on2)));
}

// ---------------- launch ------------------------------------------------------
extern "C" void kernel_launch(void* const* d_in, const int* in_sizes, int n_in,
                              void* d_out, int out_size)
{
    const float* x    = (const float*)d_in[0];
    const float* Wq   = (const float*)d_in[1];
    const float* Wk   = (const float*)d_in[2];
    const float* Wv   = (const float*)d_in[3];
    const float* Wg   = (const float*)d_in[4];
    const float* Wo   = (const float*)d_in[5];
    const float* Wb   = (const float*)d_in[6];
    const float* bb   = (const float*)d_in[7];
    const float* Wgk  = (const float*)d_in[8];
    const float* bgk  = (const float*)d_in[9];
    const float* cqw  = (const float*)d_in[10];
    const float* cqb  = (const float*)d_in[11];
    const float* ckw  = (const float*)d_in[12];
    const float* ckb  = (const float*)d_in[13];
    const float* cvw  = (const float*)d_in[14];
    const float* cvb  = (const float*)d_in[15];
    const float* A_log= (const float*)d_in[16];
    const float* D    = (const float*)d_in[17];
    const float* dtb  = (const float*)d_in[18];
    const float* onw  = (const float*)d_in[19];
    float* out = (float*)d_out;

    rope_init<<<(TLEN * 32 + 255) / 256, 256>>>();
    gemm_qkvg<<<dim3(8, 16, 4), 256>>>(x, Wq, Wk, Wv, Wg);
    small_proj<<<BT, 128>>>(x, Wb, bb, Wgk, bgk, A_log, dtb);
    conv_silu<<<dim3(TLEN / 8, 3, 2), 128>>>(cqw, cqb, ckw, ckb, cvw, cvb);
    rope_l2norm<<<2048, 256>>>();
    scan_kernel<<<dim3(16, 4), 256>>>();
    postproc<<<2048, 256>>>(D, onw);
    gemm_out<<<dim3(8, 16, 1), 256>>>(Wo, out);
}

// round 7
// speedup vs baseline: 1.8418x; 1.4376x over previous
#include <cuda_runtime.h>
#include <cstdint>
#include <math.h>

#define BATCH 2
#define TLEN  1024
#define NH    8
#define HDIM  64
#define HID   512
#define KDIM  512
#define BT    (BATCH*TLEN)

// ---------------- scratch ----------------
__device__ float g_xq[BT*KDIM];
__device__ float g_xk[BT*KDIM];
__device__ float g_xv[BT*KDIM];
__device__ float g_q [BT*KDIM];
__device__ float g_k [BT*KDIM];
__device__ float g_v [BT*KDIM];
__device__ float g_g [BT*KDIM];
__device__ float g_oc[BT*KDIM];
__device__ float g_act[BT*KDIM];
__device__ float g_beta [BT*NH];
__device__ float g_alpha[BT*NH];
__device__ float g_c1[BT*NH];
__device__ float g_cos[TLEN*32];
__device__ float g_sin[TLEN*32];

// ---------------- helpers ----------------
__device__ __forceinline__ float red32(float x)
{
#pragma unroll
    for (int m = 16; m; m >>= 1) x += __shfl_xor_sync(0xffffffffu, x, m);
    return x;
}

// ---------------- GEMM 128x128: C[2048,512] = A[2048,512] @ B[512,512]^T ------
// 8x8 microtile, double-buffered smem + register prefetch.
__global__ __launch_bounds__(256, 2) void gemm128_qkvg(const float* __restrict__ x,
    const float* __restrict__ Wq, const float* __restrict__ Wk,
    const float* __restrict__ Wv, const float* __restrict__ Wg)
{
    const float* Bw; float* C;
    switch (blockIdx.z) {
        case 0:  Bw = Wq; C = g_xq; break;
        case 1:  Bw = Wk; C = g_xk; break;
        case 2:  Bw = Wv; C = g_xv; break;
        default: Bw = Wg; C = g_g;  break;
    }
    const float* A = x;

    __shared__ __align__(16) float As[2][16][132];
    __shared__ __align__(16) float Bs[2][16][132];
    const int tid = threadIdx.x;
    const int tx = tid & 15, ty = tid >> 4;
    const int m0 = blockIdx.y * 128, n0 = blockIdx.x * 128;

    const int r0 = (tid)       >> 2, q0 = ((tid)       & 3) << 2;
    const int r1 = (tid + 256) >> 2, q1 = ((tid + 256) & 3) << 2;

    const float* aptr0 = A  + (size_t)(m0 + r0) * 512 + q0;
    const float* aptr1 = A  + (size_t)(m0 + r1) * 512 + q1;
    const float* bptr0 = Bw + (size_t)(n0 + r0) * 512 + q0;
    const float* bptr1 = Bw + (size_t)(n0 + r1) * 512 + q1;

    float acc[8][8];
#pragma unroll
    for (int i = 0; i < 8; i++)
#pragma unroll
        for (int j = 0; j < 8; j++) acc[i][j] = 0.0f;

    float4 va0 = *(const float4*)(aptr0);
    float4 va1 = *(const float4*)(aptr1);
    float4 vb0 = *(const float4*)(bptr0);
    float4 vb1 = *(const float4*)(bptr1);
    {
        As[0][q0 + 0][r0] = va0.x; As[0][q0 + 1][r0] = va0.y;
        As[0][q0 + 2][r0] = va0.z; As[0][q0 + 3][r0] = va0.w;
        As[0][q1 + 0][r1] = va1.x; As[0][q1 + 1][r1] = va1.y;
        As[0][q1 + 2][r1] = va1.z; As[0][q1 + 3][r1] = va1.w;
        Bs[0][q0 + 0][r0] = vb0.x; Bs[0][q0 + 1][r0] = vb0.y;
        Bs[0][q0 + 2][r0] = vb0.z; Bs[0][q0 + 3][r0] = vb0.w;
        Bs[0][q1 + 0][r1] = vb1.x; Bs[0][q1 + 1][r1] = vb1.y;
        Bs[0][q1 + 2][r1] = vb1.z; Bs[0][q1 + 3][r1] = vb1.w;
    }
    __syncthreads();

    for (int kt = 0; kt < 32; kt++) {
        const int cur = kt & 1;
        if (kt + 1 < 32) {
            int ko = (kt + 1) * 16;
            va0 = *(const float4*)(aptr0 + ko);
            va1 = *(const float4*)(aptr1 + ko);
            vb0 = *(const float4*)(bptr0 + ko);
            vb1 = *(const float4*)(bptr1 + ko);
        }
#pragma unroll
        for (int kk = 0; kk < 16; kk++) {
            float4 a0 = *(const float4*)&As[cur][kk][ty * 8];
            float4 a1 = *(const float4*)&As[cur][kk][ty * 8 + 4];
            float4 b0 = *(const float4*)&Bs[cur][kk][tx * 8];
            float4 b1 = *(const float4*)&Bs[cur][kk][tx * 8 + 4];
            float av[8] = {a0.x, a0.y, a0.z, a0.w, a1.x, a1.y, a1.z, a1.w};
            float bv[8] = {b0.x, b0.y, b0.z, b0.w, b1.x, b1.y, b1.z, b1.w};
#pragma unroll
            for (int i = 0; i < 8; i++)
#pragma unroll
                for (int j = 0; j < 8; j++)
                    acc[i][j] = fmaf(av[i], bv[j], acc[i][j]);
        }
        if (kt + 1 < 32) {
            const int nxt = cur ^ 1;
            As[nxt][q0 + 0][r0] = va0.x; As[nxt][q0 + 1][r0] = va0.y;
            As[nxt][q0 + 2][r0] = va0.z; As[nxt][q0 + 3][r0] = va0.w;
            As[nxt][q1 + 0][r1] = va1.x; As[nxt][q1 + 1][r1] = va1.y;
            As[nxt][q1 + 2][r1] = va1.z; As[nxt][q1 + 3][r1] = va1.w;
            Bs[nxt][q0 + 0][r0] = vb0.x; Bs[nxt][q0 + 1][r0] = vb0.y;
            Bs[nxt][q0 + 2][r0] = vb0.z; Bs[nxt][q0 + 3][r0] = vb0.w;
            Bs[nxt][q1 + 0][r1] = vb1.x; Bs[nxt][q1 + 1][r1] = vb1.y;
            Bs[nxt][q1 + 2][r1] = vb1.z; Bs[nxt][q1 + 3][r1] = vb1.w;
            __syncthreads();
        }
    }
#pragma unroll
    for (int i = 0; i < 8; i++) {
        float* crow = C + (size_t)(m0 + ty * 8 + i) * 512 + n0 + tx * 8;
        *(float4*)(crow)     = make_float4(acc[i][0], acc[i][1], acc[i][2], acc[i][3]);
        *(float4*)(crow + 4) = make_float4(acc[i][4], acc[i][5], acc[i][6], acc[i][7]);
    }
}

// ---------------- GEMM 128x64 (R6, proven) for the output projection ----------
__device__ __forceinline__ void gemm_body(const float* __restrict__ A,
                                          const float* __restrict__ Bw,
                                          float* __restrict__ C)
{
    __shared__ __align__(16) float As[2][16][132];
    __shared__ __align__(16) float Bs[2][16][68];
    const int tid = threadIdx.x;
    const int tx = tid & 15, ty = tid >> 4;
    const int m0 = blockIdx.y * 128, n0 = blockIdx.x * 64;

    const int arow0 = (tid)       >> 2, akq0 = ((tid)       & 3) << 2;
    const int arow1 = (tid + 256) >> 2, akq1 = ((tid + 256) & 3) << 2;
    const int brow  = tid >> 2,         bkq  = (tid & 3) << 2;

    const float* aptr0 = A  + (size_t)(m0 + arow0) * 512 + akq0;
    const float* aptr1 = A  + (size_t)(m0 + arow1) * 512 + akq1;
    const float* bptr  = Bw + (size_t)(n0 + brow)  * 512 + bkq;

    float acc[8][4];
#pragma unroll
    for (int i = 0; i < 8; i++)
#pragma unroll
        for (int j = 0; j < 4; j++) acc[i][j] = 0.0f;

    float4 va0 = *(const float4*)(aptr0);
    float4 va1 = *(const float4*)(aptr1);
    float4 vb  = *(const float4*)(bptr);
    {
        As[0][akq0 + 0][arow0] = va0.x; As[0][akq0 + 1][arow0] = va0.y;
        As[0][akq0 + 2][arow0] = va0.z; As[0][akq0 + 3][arow0] = va0.w;
        As[0][akq1 + 0][arow1] = va1.x; As[0][akq1 + 1][arow1] = va1.y;
        As[0][akq1 + 2][arow1] = va1.z; As[0][akq1 + 3][arow1] = va1.w;
        Bs[0][bkq + 0][brow] = vb.x; Bs[0][bkq + 1][brow] = vb.y;
        Bs[0][bkq + 2][brow] = vb.z; Bs[0][bkq + 3][brow] = vb.w;
    }
    __syncthreads();

    for (int kt = 0; kt < 32; kt++) {
        const int cur = kt & 1;
        if (kt + 1 < 32) {
            int ko = (kt + 1) * 16;
            va0 = *(const float4*)(aptr0 + ko);
            va1 = *(const float4*)(aptr1 + ko);
            vb  = *(const float4*)(bptr  + ko);
        }
#pragma unroll
        for (int kk = 0; kk < 16; kk++) {
            float4 a0 = *(const float4*)&As[cur][kk][ty * 8];
            float4 a1 = *(const float4*)&As[cur][kk][ty * 8 + 4];
            float4 b0 = *(const float4*)&Bs[cur][kk][tx * 4];
            float av[8] = {a0.x, a0.y, a0.z, a0.w, a1.x, a1.y, a1.z, a1.w};
            float bv[4] = {b0.x, b0.y, b0.z, b0.w};
#pragma unroll
            for (int i = 0; i < 8; i++)
#pragma unroll
                for (int j = 0; j < 4; j++)
                    acc[i][j] = fmaf(av[i], bv[j], acc[i][j]);
        }
        if (kt + 1 < 32) {
            const int nxt = cur ^ 1;
            As[nxt][akq0 + 0][arow0] = va0.x; As[nxt][akq0 + 1][arow0] = va0.y;
            As[nxt][akq0 + 2][arow0] = va0.z; As[nxt][akq0 + 3][arow0] = va0.w;
            As[nxt][akq1 + 0][arow1] = va1.x; As[nxt][akq1 + 1][arow1] = va1.y;
            As[nxt][akq1 + 2][arow1] = va1.z; As[nxt][akq1 + 3][arow1] = va1.w;
            Bs[nxt][bkq + 0][brow] = vb.x; Bs[nxt][bkq + 1][brow] = vb.y;
            Bs[nxt][bkq + 2][brow] = vb.z; Bs[nxt][bkq + 3][brow] = vb.w;
            __syncthreads();
        }
    }
#pragma unroll
    for (int i = 0; i < 8; i++) {
        float4 o = make_float4(acc[i][0], acc[i][1], acc[i][2], acc[i][3]);
        *(float4*)(C + (size_t)(m0 + ty * 8 + i) * 512 + n0 + tx * 4) = o;
    }
}

__global__ __launch_bounds__(256) void gemm_out(const float* __restrict__ Wo,
                                                float* __restrict__ out)
{
    gemm_body(g_act, Wo, out);
}

// ---------------- beta / alpha small projection -------------------------------
__global__ __launch_bounds__(128) void small_proj(const float* __restrict__ x,
    const float* __restrict__ Wb, const float* __restrict__ bb,
    const float* __restrict__ Wgk, const float* __restrict__ bgk,
    const float* __restrict__ A_log, const float* __restrict__ dtb)
{
    __shared__ float xs[512];
    const int bt = blockIdx.x;
    const int tid = threadIdx.x;
    for (int i = tid; i < 512; i += 128) xs[i] = x[(size_t)bt * 512 + i];
    __syncthreads();
    const int warp = tid >> 5, lane = tid & 31;
#pragma unroll
    for (int oi = 0; oi < 4; oi++) {
        int out = warp * 4 + oi;
        const float* w = (out < 8) ? (Wb + out * 512) : (Wgk + (out - 8) * 512);
        float s = 0.0f;
#pragma unroll
        for (int i = 0; i < 16; i++) s = fmaf(xs[lane + i * 32], w[lane + i * 32], s);
        s = red32(s);
        if (lane == 0) {
            if (out < 8) {
                float z = s + bb[out];
                g_beta[bt * 8 + out] = 1.0f / (1.0f + expf(-z));
            } else {
                int h = out - 8;
                float z = s + bgk[h] + dtb[h];
                float sp = (z > 20.0f) ? z : log1pf(expf(z));
                g_alpha[bt * 8 + h] = expf(-expf(A_log[h]) * sp);
            }
        }
    }
}

// ---------------- depthwise causal conv (width 4) + silu ----------------------
__global__ __launch_bounds__(128) void conv_silu(
    const float* __restrict__ cqw, const float* __restrict__ cqb,
    const float* __restrict__ ckw, const float* __restrict__ ckb,
    const float* __restrict__ cvw, const float* __restrict__ cvb)
{
    const float *xin, *w, *bi; float* out;
    switch (blockIdx.y) {
        case 0:  xin = g_xq; w = cqw; bi = cqb; out = g_q; break;
        case 1:  xin = g_xk; w = ckw; bi = ckb; out = g_k; break;
        default: xin = g_xv; w = cvw; bi = cvb; out = g_v; break;
    }
    const int c = threadIdx.x * 4;
    const int t0 = blockIdx.x * 8;
    const int b  = blockIdx.z;

    float4 wr0 = *(const float4*)(w + (c + 0) * 4);
    float4 wr1 = *(const float4*)(w + (c + 1) * 4);
    float4 wr2 = *(const float4*)(w + (c + 2) * 4);
    float4 wr3 = *(const float4*)(w + (c + 3) * 4);
    float4 bias = *(const float4*)(bi + c);

    const float* xrow = xin + (size_t)b * TLEN * 512 + c;
    float*       orow = out + (size_t)b * TLEN * 512 + c;
    const float4 zero = make_float4(0.f, 0.f, 0.f, 0.f);

    float4 h0 = (t0 - 3 >= 0) ? *(const float4*)(xrow + (size_t)(t0 - 3) * 512) : zero;
    float4 h1 = (t0 - 2 >= 0) ? *(const float4*)(xrow + (size_t)(t0 - 2) * 512) : zero;
    float4 h2 = (t0 - 1 >= 0) ? *(const float4*)(xrow + (size_t)(t0 - 1) * 512) : zero;
    float4 cur = *(const float4*)(xrow + (size_t)t0 * 512);

#pragma unroll
    for (int t = t0; t < t0 + 8; t++) {
        float4 nxt = (t + 1 < TLEN) ? *(const float4*)(xrow + (size_t)(t + 1) * 512) : zero;
        float4 acc = bias;
        acc.x = fmaf(h0.x, wr0.x, acc.x); acc.x = fmaf(h1.x, wr0.y, acc.x);
        acc.x = fmaf(h2.x, wr0.z, acc.x); acc.x = fmaf(cur.x, wr0.w, acc.x);
        acc.y = fmaf(h0.y, wr1.x, acc.y); acc.y = fmaf(h1.y, wr1.y, acc.y);
        acc.y = fmaf(h2.y, wr1.z, acc.y); acc.y = fmaf(cur.y, wr1.w, acc.y);
        acc.z = fmaf(h0.z, wr2.x, acc.z); acc.z = fmaf(h1.z, wr2.y, acc.z);
        acc.z = fmaf(h2.z, wr2.z, acc.z); acc.z = fmaf(cur.z, wr2.w, acc.z);
        acc.w = fmaf(h0.w, wr3.x, acc.w); acc.w = fmaf(h1.w, wr3.y, acc.w);
        acc.w = fmaf(h2.w, wr3.z, acc.w); acc.w = fmaf(cur.w, wr3.w, acc.w);
        float4 o;
        o.x = acc.x / (1.0f + expf(-acc.x));
        o.y = acc.y / (1.0f + expf(-acc.y));
        o.z = acc.z / (1.0f + expf(-acc.z));
        o.w = acc.w / (1.0f + expf(-acc.w));
        *(float4*)(orow + (size_t)t * 512) = o;
        h0 = h1; h1 = h2; h2 = cur; cur = nxt;
    }
}

// ---------------- RoPE tables (fp64, recomputed every launch) -----------------
__global__ void rope_init()
{
    int idx = blockIdx.x * blockDim.x + threadIdx.x;
    if (idx >= TLEN * 32) return;
    int t = idx >> 5, j = idx & 31;
    const double PI = 3.14159265358979323846;
    double ar = (double)j / 32.0;
    double sbase = 10000.0 * pow(32.0, 64.0 / 62.0);
    double inv_freq = pow(sbase, -ar);
    double freq_extra = pow(10000.0, -ar);
    double wavelen = (2.0 * PI) / freq_extra;
    double ramp = (wavelen - 1.0) / 31.0;
    ramp = ramp < 0.0 ? 0.0 : (ramp > 1.0 ? 1.0 : ramp);
    double spf = 1.0 + 31.0 * ramp;
    double f = (double)t / spf * inv_freq;
    g_cos[idx] = (float)cos(f);
    g_sin[idx] = (float)sin(f);
}

// ---------------- RoPE + l2norm, in-place on g_q / g_k ------------------------
__global__ __launch_bounds__(256) void rope_l2norm()
{
    int gw = (blockIdx.x * blockDim.x + threadIdx.x) >> 5;
    int lane = threadIdx.x & 31;
    if (gw >= BT * NH) return;
    int t = (gw >> 3) & 1023;
    int j = (2 * lane) & 31;
    float c = g_cos[t * 32 + j], s = g_sin[t * 32 + j];
    size_t base = (size_t)gw * 64;
#pragma unroll
    for (int which = 0; which < 2; which++) {
        float* p = which ? g_k : g_q;
        float x1 = p[base + 2 * lane];
        float x2 = p[base + 2 * lane + 1];
        float o1 = x1 * c - x2 * s;
        float o2 = x1 * s + x2 * c;
        float ss = red32(o1 * o1 + o2 * o2);
        float inv = 1.0f / fmaxf(sqrtf(ss), 1e-12f);
        p[base + lane]      = o1 * inv;
        p[base + 32 + lane] = o2 * inv;
    }
}

// ---------------- c1[t] = k_t . k_{t-1} precompute ----------------------------
__global__ __launch_bounds__(256) void c1_prep()
{
    int gw = (blockIdx.x * (blockDim.x >> 5)) + (threadIdx.x >> 5);
    int lane = threadIdx.x & 31;
    if (gw >= BT * NH) return;
    int h = gw & 7, bt = gw >> 3;
    int t = bt & 1023;
    float cv = 0.0f;
    if (t > 0) {
        const float* ka = g_k + (size_t)bt * 512 + h * 64;
        const float* kb = ka - 512;
        float2 xx = *(const float2*)(ka + lane * 2);
        float2 yy = *(const float2*)(kb + lane * 2);
        cv = red32(fmaf(xx.x, yy.x, xx.y * yy.y));
    }
    if (lane == 0) g_c1[(size_t)bt * 8 + h] = cv;
}

// ---------------- delta-rule scan (look-ahead pipelined) ----------------------
// u_t = a_{t-1} r_t + b_{t-1} c1_t (v_{t-1} - a_{t-1} u_{t-1}),
//   r_t = k_t^T S_{t-2}  (reduction given ~2 steps of slack),
//   c1_t = k_t . k_{t-1} (precomputed).
// S_t = a_t S_{t-1} + b_t (v_t - a_t u_t) k_t ; o_t = q_t^T S_t (pipelined red).
// grid (16 heads, 8 e-groups), 128 threads; warp = 2 e-columns, 16 lanes each.
__global__ __launch_bounds__(128) void scan_kernel()
{
    const int bh = blockIdx.x;
    const int eg = blockIdx.y;
    const int b = bh >> 3, h = bh & 7;
    const int w = threadIdx.x >> 5, lane = threadIdx.x & 31;
    const int el = lane >> 4, r = lane & 15;
    const int e  = eg * 8 + w * 2 + el;
    const int d0 = r * 4;

    const size_t head = ((size_t)b * TLEN * NH + h) * 64;
    const float* qp = g_q + head + d0;
    const float* kp = g_k + head + d0;
    const float* vpt = g_v + head + e;
    float*       op = g_oc + head + e;
    const float* apt = g_alpha + (size_t)b * TLEN * NH + h;
    const float* bpt = g_beta  + (size_t)b * TLEN * NH + h;
    const float* cpt = g_c1    + (size_t)b * TLEN * NH + h;

    float4 S = make_float4(0.f, 0.f, 0.f, 0.f);
    float u_prev = 0.f, r_use = 0.f, h1 = 0.f, oh1 = 0.f;
    float vp = 0.f, apv = 0.f, bpv = 0.f;

    // register rings: k depth 6 (ring 8), q/scalars depth 4 (ring 4)
    float4 kb[8];
    float4 qb[4];
    float  vb[4], ab[4], bb2[4], cb[4];
#pragma unroll
    for (int i = 0; i < 6; i++) kb[i] = *(const float4*)(kp + (size_t)i * 512);
    kb[6] = kb[7] = make_float4(0.f, 0.f, 0.f, 0.f);
#pragma unroll
    for (int i = 0; i < 4; i++) {
        qb[i]  = *(const float4*)(qp + (size_t)i * 512);
        vb[i]  = vpt[(size_t)i * 512];
        ab[i]  = apt[(size_t)i * 8];
        bb2[i] = bpt[(size_t)i * 8];
        cb[i]  = cpt[(size_t)i * 8];
    }

#pragma unroll 8
    for (int t = 0; t < TLEN; t++) {
        const float4 kc  = kb[t & 7];
        const float4 kf  = kb[(t + 2) & 7];   // k_{t+2} for r partial
        const float4 qc  = qb[t & 3];
        const float  vc  = vb[t & 3];
        const float  ac  = ab[t & 3];
        const float  bc  = bb2[t & 3];
        const float  c1c = cb[t & 3];

        // scalar recurrence for u_t (short chain)
        float u = fmaf(apv, r_use, bpv * c1c * fmaf(-apv, u_prev, vp));
        // state update S_{t-1} -> S_t
        float coef = bc * fmaf(-ac, u, vc);
        S.x = fmaf(kc.x, coef, ac * S.x);
        S.y = fmaf(kc.y, coef, ac * S.y);
        S.z = fmaf(kc.z, coef, ac * S.z);
        S.w = fmaf(kc.w, coef, ac * S.w);

        // finish r_{t+1} reduction (stages 3,4)
        float h2 = h1 + __shfl_xor_sync(0xffffffffu, h1, 2);
        float r_next = h2 + __shfl_xor_sync(0xffffffffu, h2, 1);
        // finish o_{t-1} reduction (stages 3,4) and store
        float og = oh1 + __shfl_xor_sync(0xffffffffu, oh1, 2);
        float o_fin = og + __shfl_xor_sync(0xffffffffu, og, 1);
        if (r == 0 && t > 0) op[(size_t)(t - 1) * 512] = o_fin;

        // new partials from fresh S_t + reduction stages 1,2
        float rp = fmaf(kf.x, S.x, fmaf(kf.y, S.y, fmaf(kf.z, S.z, kf.w * S.w)));
        float rh = rp + __shfl_xor_sync(0xffffffffu, rp, 8);
        h1 = rh + __shfl_xor_sync(0xffffffffu, rh, 4);
        float opp = fmaf(qc.x, S.x, fmaf(qc.y, S.y, fmaf(qc.z, S.z, qc.w * S.w)));
        float oh = opp + __shfl_xor_sync(0xffffffffu, opp, 8);
        oh1 = oh + __shfl_xor_sync(0xffffffffu, oh, 4);

        // shift carries
        u_prev = u; r_use = r_next;
        vp = vc; apv = ac; bpv = bc;

        // prefetch (deep: k at +6, q/scalars at +4)
        int t6 = t + 6; t6 = (t6 < TLEN) ? t6 : (TLEN - 1);
        int t4 = t + 4; t4 = (t4 < TLEN) ? t4 : (TLEN - 1);
        kb[(t + 6) & 7] = *(const float4*)(kp + (size_t)t6 * 512);
        qb[(t + 4) & 3] = *(const float4*)(qp + (size_t)t4 * 512);
        vb[(t + 4) & 3]  = vpt[(size_t)t4 * 512];
        ab[(t + 4) & 3]  = apt[(size_t)t4 * 8];
        bb2[(t + 4) & 3] = bpt[(size_t)t4 * 8];
        cb[(t + 4) & 3]  = cpt[(size_t)t4 * 8];
    }
    // epilogue: finish and store o_{T-1}
    float og = oh1 + __shfl_xor_sync(0xffffffffu, oh1, 2);
    float o_fin = og + __shfl_xor_sync(0xffffffffu, og, 1);
    if (r == 0) op[(size_t)(TLEN - 1) * 512] = o_fin;
}

// ---------------- post: +D*v, RMS norm, gate ----------------------------------
__global__ __launch_bounds__(256) void postproc(const float* __restrict__ D,
                                                const float* __restrict__ onw)
{
    int gw = (blockIdx.x * blockDim.x + threadIdx.x) >> 5;
    int lane = threadIdx.x & 31;
    if (gw >= BT * NH) return;
    int h = gw & 7;
    size_t base = (size_t)gw * 64;
    float d = D[h];
    float o1 = g_oc[base + lane]      + d * g_v[base + lane];
    float o2 = g_oc[base + 32 + lane] + d * g_v[base + 32 + lane];
    float ss = red32(o1 * o1 + o2 * o2);
    float sc = rsqrtf(ss * (1.0f / 64.0f) + 1e-6f);
    float on1 = o1 * sc * onw[lane];
    float on2 = o2 * sc * onw[32 + lane];
    float g1 = g_g[base + lane], g2 = g_g[base + 32 + lane];
    g_act[base + lane]      = g1 * (on1 / (1.0f + expf(-on1)));
    g_act[base + 32 + lane] = g2 * (on2 / (1.0f + expf(-on2)));
}

// ---------------- launch ------------------------------------------------------
extern "C" void kernel_launch(void* const* d_in, const int* in_sizes, int n_in,
                              void* d_out, int out_size)
{
    const float* x    = (const float*)d_in[0];
    const float* Wq   = (const float*)d_in[1];
    const float* Wk   = (const float*)d_in[2];
    const float* Wv   = (const float*)d_in[3];
    const float* Wg   = (const float*)d_in[4];
    const float* Wo   = (const float*)d_in[5];
    const float* Wb   = (const float*)d_in[6];
    const float* bb   = (const float*)d_in[7];
    const float* Wgk  = (const float*)d_in[8];
    const float* bgk  = (const float*)d_in[9];
    const float* cqw  = (const float*)d_in[10];
    const float* cqb  = (const float*)d_in[11];
    const float* ckw  = (const float*)d_in[12];
    const float* ckb  = (const float*)d_in[13];
    const float* cvw  = (const float*)d_in[14];
    const float* cvb  = (const float*)d_in[15];
    const float* A_log= (const float*)d_in[16];
    const float* D    = (const float*)d_in[17];
    const float* dtb  = (const float*)d_in[18];
    const float* onw  = (const float*)d_in[19];
    float* out = (float*)d_out;

    rope_init<<<(TLEN * 32 + 255) / 256, 256>>>();
    gemm128_qkvg<<<dim3(4, 16, 4), 256>>>(x, Wq, Wk, Wv, Wg);
    small_proj<<<BT, 128>>>(x, Wb, bb, Wgk, bgk, A_log, dtb);
    conv_silu<<<dim3(TLEN / 8, 3, 2), 128>>>(cqw, cqb, ckw, ckb, cvw, cvb);
    rope_l2norm<<<2048, 256>>>();
    c1_prep<<<(BT * NH + 7) / 8, 256>>>();
    scan_kernel<<<dim3(16, 8), 128>>>();
    postproc<<<2048, 256>>>(D, onw);
    gemm_out<<<dim3(8, 16, 1), 256>>>(Wo, out);
}

// round 8
// speedup vs baseline: 1.9301x; 1.0479x over previous
#include <cuda_runtime.h>
#include <cstdint>
#include <math.h>

#define BATCH 2
#define TLEN  1024
#define NH    8
#define HDIM  64
#define HID   512
#define KDIM  512
#define BT    (BATCH*TLEN)
#define PADROWS 8

// ---------------- scratch (q/k/v + gating padded for unconditional prefetch) --
__device__ float g_xq[BT*KDIM];
__device__ float g_xk[BT*KDIM];
__device__ float g_xv[BT*KDIM];
__device__ float g_q [BT*KDIM + PADROWS*KDIM];
__device__ float g_k [BT*KDIM + PADROWS*KDIM];
__device__ float g_v [BT*KDIM + PADROWS*KDIM];
__device__ float g_g [BT*KDIM];
__device__ float g_oc[BT*KDIM];
__device__ float g_act[BT*KDIM];
__device__ float g_p0[BT*KDIM];
__device__ float g_p1[BT*KDIM];
__device__ float g_beta [BT*NH + PADROWS*NH];
__device__ float g_alpha[BT*NH + PADROWS*NH];
__device__ float g_c1   [BT*NH + PADROWS*NH];
__device__ float g_cos[TLEN*32];
__device__ float g_sin[TLEN*32];

// ---------------- helpers ----------------
__device__ __forceinline__ float red32(float x)
{
#pragma unroll
    for (int m = 16; m; m >>= 1) x += __shfl_xor_sync(0xffffffffu, x, m);
    return x;
}

// ---------------- GEMM 128x128 body, parametric K range -----------------------
// C[m0:128, n0:128] (+)= A[m0:128, kb:kb+KT*16] @ B[n0:128, kb:..]^T
__device__ __forceinline__ void gemm128_body(const float* __restrict__ A,
                                             const float* __restrict__ Bw,
                                             float* __restrict__ C,
                                             int kbase, int KT)
{
    __shared__ __align__(16) float As[2][16][132];
    __shared__ __align__(16) float Bs[2][16][132];
    const int tid = threadIdx.x;
    const int tx = tid & 15, ty = tid >> 4;
    const int m0 = blockIdx.y * 128, n0 = blockIdx.x * 128;

    const int r0 = (tid)       >> 2, q0 = ((tid)       & 3) << 2;
    const int r1 = (tid + 256) >> 2, q1 = ((tid + 256) & 3) << 2;

    const float* aptr0 = A  + (size_t)(m0 + r0) * 512 + kbase + q0;
    const float* aptr1 = A  + (size_t)(m0 + r1) * 512 + kbase + q1;
    const float* bptr0 = Bw + (size_t)(n0 + r0) * 512 + kbase + q0;
    const float* bptr1 = Bw + (size_t)(n0 + r1) * 512 + kbase + q1;

    float acc[8][8];
#pragma unroll
    for (int i = 0; i < 8; i++)
#pragma unroll
        for (int j = 0; j < 8; j++) acc[i][j] = 0.0f;

    float4 va0 = *(const float4*)(aptr0);
    float4 va1 = *(const float4*)(aptr1);
    float4 vb0 = *(const float4*)(bptr0);
    float4 vb1 = *(const float4*)(bptr1);
    {
        As[0][q0 + 0][r0] = va0.x; As[0][q0 + 1][r0] = va0.y;
        As[0][q0 + 2][r0] = va0.z; As[0][q0 + 3][r0] = va0.w;
        As[0][q1 + 0][r1] = va1.x; As[0][q1 + 1][r1] = va1.y;
        As[0][q1 + 2][r1] = va1.z; As[0][q1 + 3][r1] = va1.w;
        Bs[0][q0 + 0][r0] = vb0.x; Bs[0][q0 + 1][r0] = vb0.y;
        Bs[0][q0 + 2][r0] = vb0.z; Bs[0][q0 + 3][r0] = vb0.w;
        Bs[0][q1 + 0][r1] = vb1.x; Bs[0][q1 + 1][r1] = vb1.y;
        Bs[0][q1 + 2][r1] = vb1.z; Bs[0][q1 + 3][r1] = vb1.w;
    }
    __syncthreads();

    for (int kt = 0; kt < KT; kt++) {
        const int cur = kt & 1;
        if (kt + 1 < KT) {
            int ko = (kt + 1) * 16;
            va0 = *(const float4*)(aptr0 + ko);
            va1 = *(const float4*)(aptr1 + ko);
            vb0 = *(const float4*)(bptr0 + ko);
            vb1 = *(const float4*)(bptr1 + ko);
        }
#pragma unroll
        for (int kk = 0; kk < 16; kk++) {
            float4 a0 = *(const float4*)&As[cur][kk][ty * 8];
            float4 a1 = *(const float4*)&As[cur][kk][ty * 8 + 4];
            float4 b0 = *(const float4*)&Bs[cur][kk][tx * 8];
            float4 b1 = *(const float4*)&Bs[cur][kk][tx * 8 + 4];
            float av[8] = {a0.x, a0.y, a0.z, a0.w, a1.x, a1.y, a1.z, a1.w};
            float bv[8] = {b0.x, b0.y, b0.z, b0.w, b1.x, b1.y, b1.z, b1.w};
#pragma unroll
            for (int i = 0; i < 8; i++)
#pragma unroll
                for (int j = 0; j < 8; j++)
                    acc[i][j] = fmaf(av[i], bv[j], acc[i][j]);
        }
        if (kt + 1 < KT) {
            const int nxt = cur ^ 1;
            As[nxt][q0 + 0][r0] = va0.x; As[nxt][q0 + 1][r0] = va0.y;
            As[nxt][q0 + 2][r0] = va0.z; As[nxt][q0 + 3][r0] = va0.w;
            As[nxt][q1 + 0][r1] = va1.x; As[nxt][q1 + 1][r1] = va1.y;
            As[nxt][q1 + 2][r1] = va1.z; As[nxt][q1 + 3][r1] = va1.w;
            Bs[nxt][q0 + 0][r0] = vb0.x; Bs[nxt][q0 + 1][r0] = vb0.y;
            Bs[nxt][q0 + 2][r0] = vb0.z; Bs[nxt][q0 + 3][r0] = vb0.w;
            Bs[nxt][q1 + 0][r1] = vb1.x; Bs[nxt][q1 + 1][r1] = vb1.y;
            Bs[nxt][q1 + 2][r1] = vb1.z; Bs[nxt][q1 + 3][r1] = vb1.w;
            __syncthreads();
        }
    }
#pragma unroll
    for (int i = 0; i < 8; i++) {
        float* crow = C + (size_t)(m0 + ty * 8 + i) * 512 + n0 + tx * 8;
        *(float4*)(crow)     = make_float4(acc[i][0], acc[i][1], acc[i][2], acc[i][3]);
        *(float4*)(crow + 4) = make_float4(acc[i][4], acc[i][5], acc[i][6], acc[i][7]);
    }
}

__global__ __launch_bounds__(256, 2) void gemm128_qkvg(const float* __restrict__ x,
    const float* __restrict__ Wq, const float* __restrict__ Wk,
    const float* __restrict__ Wv, const float* __restrict__ Wg)
{
    const float* Bw; float* C;
    switch (blockIdx.z) {
        case 0:  Bw = Wq; C = g_xq; break;
        case 1:  Bw = Wk; C = g_xk; break;
        case 2:  Bw = Wv; C = g_xv; break;
        default: Bw = Wg; C = g_g;  break;
    }
    gemm128_body(x, Bw, C, 0, 32);
}

// output projection: split-K x2 into partial buffers
__global__ __launch_bounds__(256, 2) void gemm_out_k(const float* __restrict__ Wo)
{
    float* C = blockIdx.z ? g_p1 : g_p0;
    gemm128_body(g_act, Wo, C, blockIdx.z * 256, 16);
}

__global__ __launch_bounds__(256) void add_out(float* __restrict__ out)
{
    int i = blockIdx.x * blockDim.x + threadIdx.x;
    if (i >= BT * KDIM / 4) return;
    float4 a = *(const float4*)(g_p0 + (size_t)i * 4);
    float4 b = *(const float4*)(g_p1 + (size_t)i * 4);
    *(float4*)(out + (size_t)i * 4) =
        make_float4(a.x + b.x, a.y + b.y, a.z + b.z, a.w + b.w);
}

// ---------------- beta / alpha small projection -------------------------------
__global__ __launch_bounds__(128) void small_proj(const float* __restrict__ x,
    const float* __restrict__ Wb, const float* __restrict__ bb,
    const float* __restrict__ Wgk, const float* __restrict__ bgk,
    const float* __restrict__ A_log, const float* __restrict__ dtb)
{
    __shared__ float xs[512];
    const int bt = blockIdx.x;
    const int tid = threadIdx.x;
    for (int i = tid; i < 512; i += 128) xs[i] = x[(size_t)bt * 512 + i];
    __syncthreads();
    const int warp = tid >> 5, lane = tid & 31;
#pragma unroll
    for (int oi = 0; oi < 4; oi++) {
        int out = warp * 4 + oi;
        const float* w = (out < 8) ? (Wb + out * 512) : (Wgk + (out - 8) * 512);
        float s = 0.0f;
#pragma unroll
        for (int i = 0; i < 16; i++) s = fmaf(xs[lane + i * 32], w[lane + i * 32], s);
        s = red32(s);
        if (lane == 0) {
            if (out < 8) {
                float z = s + bb[out];
                g_beta[bt * 8 + out] = 1.0f / (1.0f + expf(-z));
            } else {
                int h = out - 8;
                float z = s + bgk[h] + dtb[h];
                float sp = (z > 20.0f) ? z : log1pf(expf(z));
                g_alpha[bt * 8 + h] = expf(-expf(A_log[h]) * sp);
            }
        }
    }
}

// ---------------- depthwise causal conv (width 4) + silu ----------------------
__global__ __launch_bounds__(128) void conv_silu(
    const float* __restrict__ cqw, const float* __restrict__ cqb,
    const float* __restrict__ ckw, const float* __restrict__ ckb,
    const float* __restrict__ cvw, const float* __restrict__ cvb)
{
    const float *xin, *w, *bi; float* out;
    switch (blockIdx.y) {
        case 0:  xin = g_xq; w = cqw; bi = cqb; out = g_q; break;
        case 1:  xin = g_xk; w = ckw; bi = ckb; out = g_k; break;
        default: xin = g_xv; w = cvw; bi = cvb; out = g_v; break;
    }
    const int c = threadIdx.x * 4;
    const int t0 = blockIdx.x * 4;
    const int b  = blockIdx.z;

    float4 wr0 = *(const float4*)(w + (c + 0) * 4);
    float4 wr1 = *(const float4*)(w + (c + 1) * 4);
    float4 wr2 = *(const float4*)(w + (c + 2) * 4);
    float4 wr3 = *(const float4*)(w + (c + 3) * 4);
    float4 bias = *(const float4*)(bi + c);

    const float* xrow = xin + (size_t)b * TLEN * 512 + c;
    float*       orow = out + (size_t)b * TLEN * 512 + c;
    const float4 zero = make_float4(0.f, 0.f, 0.f, 0.f);

    float4 h0 = (t0 - 3 >= 0) ? *(const float4*)(xrow + (size_t)(t0 - 3) * 512) : zero;
    float4 h1 = (t0 - 2 >= 0) ? *(const float4*)(xrow + (size_t)(t0 - 2) * 512) : zero;
    float4 h2 = (t0 - 1 >= 0) ? *(const float4*)(xrow + (size_t)(t0 - 1) * 512) : zero;
    float4 cur = *(const float4*)(xrow + (size_t)t0 * 512);

#pragma unroll
    for (int t = t0; t < t0 + 4; t++) {
        float4 nxt = (t + 1 < TLEN) ? *(const float4*)(xrow + (size_t)(t + 1) * 512) : zero;
        float4 acc = bias;
        acc.x = fmaf(h0.x, wr0.x, acc.x); acc.x = fmaf(h1.x, wr0.y, acc.x);
        acc.x = fmaf(h2.x, wr0.z, acc.x); acc.x = fmaf(cur.x, wr0.w, acc.x);
        acc.y = fmaf(h0.y, wr1.x, acc.y); acc.y = fmaf(h1.y, wr1.y, acc.y);
        acc.y = fmaf(h2.y, wr1.z, acc.y); acc.y = fmaf(cur.y, wr1.w, acc.y);
        acc.z = fmaf(h0.z, wr2.x, acc.z); acc.z = fmaf(h1.z, wr2.y, acc.z);
        acc.z = fmaf(h2.z, wr2.z, acc.z); acc.z = fmaf(cur.z, wr2.w, acc.z);
        acc.w = fmaf(h0.w, wr3.x, acc.w); acc.w = fmaf(h1.w, wr3.y, acc.w);
        acc.w = fmaf(h2.w, wr3.z, acc.w); acc.w = fmaf(cur.w, wr3.w, acc.w);
        float4 o;
        o.x = acc.x / (1.0f + expf(-acc.x));
        o.y = acc.y / (1.0f + expf(-acc.y));
        o.z = acc.z / (1.0f + expf(-acc.z));
        o.w = acc.w / (1.0f + expf(-acc.w));
        *(float4*)(orow + (size_t)t * 512) = o;
        h0 = h1; h1 = h2; h2 = cur; cur = nxt;
    }
}

// ---------------- RoPE tables (fp64, recomputed every launch) -----------------
__global__ void rope_init()
{
    int idx = blockIdx.x * blockDim.x + threadIdx.x;
    if (idx >= TLEN * 32) return;
    int t = idx >> 5, j = idx & 31;
    const double PI = 3.14159265358979323846;
    double ar = (double)j / 32.0;
    double sbase = 10000.0 * pow(32.0, 64.0 / 62.0);
    double inv_freq = pow(sbase, -ar);
    double freq_extra = pow(10000.0, -ar);
    double wavelen = (2.0 * PI) / freq_extra;
    double ramp = (wavelen - 1.0) / 31.0;
    ramp = ramp < 0.0 ? 0.0 : (ramp > 1.0 ? 1.0 : ramp);
    double spf = 1.0 + 31.0 * ramp;
    double f = (double)t / spf * inv_freq;
    g_cos[idx] = (float)cos(f);
    g_sin[idx] = (float)sin(f);
}

// ---------------- RoPE + l2norm, in-place on g_q / g_k ------------------------
__global__ __launch_bounds__(256) void rope_l2norm()
{
    int gw = (blockIdx.x * blockDim.x + threadIdx.x) >> 5;
    int lane = threadIdx.x & 31;
    if (gw >= BT * NH) return;
    int t = (gw >> 3) & 1023;
    int j = (2 * lane) & 31;
    float c = g_cos[t * 32 + j], s = g_sin[t * 32 + j];
    size_t base = (size_t)gw * 64;
#pragma unroll
    for (int which = 0; which < 2; which++) {
        float* p = which ? g_k : g_q;
        float x1 = p[base + 2 * lane];
        float x2 = p[base + 2 * lane + 1];
        float o1 = x1 * c - x2 * s;
        float o2 = x1 * s + x2 * c;
        float ss = red32(o1 * o1 + o2 * o2);
        float inv = 1.0f / fmaxf(sqrtf(ss), 1e-12f);
        p[base + lane]      = o1 * inv;
        p[base + 32 + lane] = o2 * inv;
    }
}

// ---------------- c1[t] = k_t . k_{t-1} precompute ----------------------------
__global__ __launch_bounds__(256) void c1_prep()
{
    int gw = (blockIdx.x * (blockDim.x >> 5)) + (threadIdx.x >> 5);
    int lane = threadIdx.x & 31;
    if (gw >= BT * NH) return;
    int h = gw & 7, bt = gw >> 3;
    int t = bt & 1023;
    float cv = 0.0f;
    if (t > 0) {
        const float* ka = g_k + (size_t)bt * 512 + h * 64;
        const float* kb = ka - 512;
        float2 xx = *(const float2*)(ka + lane * 2);
        float2 yy = *(const float2*)(kb + lane * 2);
        cv = red32(fmaf(xx.x, yy.x, xx.y * yy.y));
    }
    if (lane == 0) g_c1[(size_t)bt * 8 + h] = cv;
}

// ---------------- delta-rule scan (look-ahead pipelined, pointer-bump) --------
// u_t = a_{t-1} r_t + b_{t-1} c1_t (v_{t-1} - a_{t-1} u_{t-1}),
//   r_t = k_t^T S_{t-2}, c1_t = k_t.k_{t-1} (precomputed).
// Prefetch is unconditional into zero-padded arrays (pad never stored; stays 0).
__global__ __launch_bounds__(128) void scan_kernel()
{
    const int bh = blockIdx.x;
    const int eg = blockIdx.y;
    const int b = bh >> 3, h = bh & 7;
    const int w = threadIdx.x >> 5, lane = threadIdx.x & 31;
    const int el = lane >> 4, r = lane & 15;
    const int e  = eg * 8 + w * 2 + el;
    const int d0 = r * 4;

    const size_t head = ((size_t)b * TLEN * NH + h) * 64;
    const float* qp  = g_q + head + d0;
    const float* kp  = g_k + head + d0;
    const float* vpt = g_v + head + e;
    float*       op  = g_oc + head + e;
    const float* apt = g_alpha + (size_t)b * TLEN * NH + h;
    const float* bpt = g_beta  + (size_t)b * TLEN * NH + h;
    const float* cpt = g_c1    + (size_t)b * TLEN * NH + h;

    float4 S = make_float4(0.f, 0.f, 0.f, 0.f);
    float u_prev = 0.f, r_use = 0.f, h1 = 0.f, oh1 = 0.f;
    float vp = 0.f, apv = 0.f, bpv = 0.f;

    float4 kb[8];
    float4 qb[4];
    float  vb[4], ab[4], bb2[4], cb[4];
#pragma unroll
    for (int i = 0; i < 6; i++) kb[i] = *(const float4*)(kp + (size_t)i * 512);
    kb[6] = kb[7] = make_float4(0.f, 0.f, 0.f, 0.f);
#pragma unroll
    for (int i = 0; i < 4; i++) {
        qb[i]  = *(const float4*)(qp + (size_t)i * 512);
        vb[i]  = vpt[(size_t)i * 512];
        ab[i]  = apt[(size_t)i * 8];
        bb2[i] = bpt[(size_t)i * 8];
        cb[i]  = cpt[(size_t)i * 8];
    }

#pragma unroll 8
    for (int t = 0; t < TLEN; t++) {
        const float4 kc  = kb[t & 7];
        const float4 kf  = kb[(t + 2) & 7];   // k_{t+2} for r partial
        const float4 qc  = qb[t & 3];
        const float  vc  = vb[t & 3];
        const float  ac  = ab[t & 3];
        const float  bc  = bb2[t & 3];
        const float  c1c = cb[t & 3];

        float u = fmaf(apv, r_use, bpv * c1c * fmaf(-apv, u_prev, vp));
        float coef = bc * fmaf(-ac, u, vc);
        S.x = fmaf(kc.x, coef, ac * S.x);
        S.y = fmaf(kc.y, coef, ac * S.y);
        S.z = fmaf(kc.z, coef, ac * S.z);
        S.w = fmaf(kc.w, coef, ac * S.w);

        float h2 = h1 + __shfl_xor_sync(0xffffffffu, h1, 2);
        float r_next = h2 + __shfl_xor_sync(0xffffffffu, h2, 1);
        float og = oh1 + __shfl_xor_sync(0xffffffffu, oh1, 2);
        float o_fin = og + __shfl_xor_sync(0xffffffffu, og, 1);
        if (r == 0 && t > 0) op[-512] = o_fin;

        float rp = fmaf(kf.x, S.x, fmaf(kf.y, S.y, fmaf(kf.z, S.z, kf.w * S.w)));
        float rh = rp + __shfl_xor_sync(0xffffffffu, rp, 8);
        h1 = rh + __shfl_xor_sync(0xffffffffu, rh, 4);
        float opp = fmaf(qc.x, S.x, fmaf(qc.y, S.y, fmaf(qc.z, S.z, qc.w * S.w)));
        float oh = opp + __shfl_xor_sync(0xffffffffu, opp, 8);
        oh1 = oh + __shfl_xor_sync(0xffffffffu, oh, 4);

        u_prev = u; r_use = r_next;
        vp = vc; apv = ac; bpv = bc;

        // unconditional prefetch from padded arrays (padding is zero)
        kb[(t + 6) & 7] = *(const float4*)(kp + 6 * 512);
        qb[(t + 4) & 3] = *(const float4*)(qp + 4 * 512);
        vb[(t + 4) & 3]  = vpt[4 * 512];
        ab[(t + 4) & 3]  = apt[4 * 8];
        bb2[(t + 4) & 3] = bpt[4 * 8];
        cb[(t + 4) & 3]  = cpt[4 * 8];
        kp += 512; qp += 512; vpt += 512; op += 512;
        apt += 8; bpt += 8; cpt += 8;
    }
    float og = oh1 + __shfl_xor_sync(0xffffffffu, oh1, 2);
    float o_fin = og + __shfl_xor_sync(0xffffffffu, og, 1);
    if (r == 0) op[-512] = o_fin;
}

// ---------------- post: +D*v, RMS norm, gate ----------------------------------
__global__ __launch_bounds__(256) void postproc(const float* __restrict__ D,
                                                const float* __restrict__ onw)
{
    int gw = (blockIdx.x * blockDim.x + threadIdx.x) >> 5;
    int lane = threadIdx.x & 31;
    if (gw >= BT * NH) return;
    int h = gw & 7;
    size_t base = (size_t)gw * 64;
    float d = D[h];
    float o1 = g_oc[base + lane]      + d * g_v[base + lane];
    float o2 = g_oc[base + 32 + lane] + d * g_v[base + 32 + lane];
    float ss = red32(o1 * o1 + o2 * o2);
    float sc = rsqrtf(ss * (1.0f / 64.0f) + 1e-6f);
    float on1 = o1 * sc * onw[lane];
    float on2 = o2 * sc * onw[32 + lane];
    float g1 = g_g[base + lane], g2 = g_g[base + 32 + lane];
    g_act[base + lane]      = g1 * (on1 / (1.0f + expf(-on1)));
    g_act[base + 32 + lane] = g2 * (on2 / (1.0f + expf(-on2)));
}

// ---------------- launch ------------------------------------------------------
extern "C" void kernel_launch(void* const* d_in, const int* in_sizes, int n_in,
                              void* d_out, int out_size)
{
    const float* x    = (const float*)d_in[0];
    const float* Wq   = (const float*)d_in[1];
    const float* Wk   = (const float*)d_in[2];
    const float* Wv   = (const float*)d_in[3];
    const float* Wg   = (const float*)d_in[4];
    const float* Wo   = (const float*)d_in[5];
    const float* Wb   = (const float*)d_in[6];
    const float* bb   = (const float*)d_in[7];
    const float* Wgk  = (const float*)d_in[8];
    const float* bgk  = (const float*)d_in[9];
    const float* cqw  = (const float*)d_in[10];
    const float* cqb  = (const float*)d_in[11];
    const float* ckw  = (const float*)d_in[12];
    const float* ckb  = (const float*)d_in[13];
    const float* cvw  = (const float*)d_in[14];
    const float* cvb  = (const float*)d_in[15];
    const float* A_log= (const float*)d_in[16];
    const float* D    = (const float*)d_in[17];
    const float* dtb  = (const float*)d_in[18];
    const float* onw  = (const float*)d_in[19];
    float* out = (float*)d_out;

    rope_init<<<(TLEN * 32 + 255) / 256, 256>>>();
    gemm128_qkvg<<<dim3(4, 16, 4), 256>>>(x, Wq, Wk, Wv, Wg);
    small_proj<<<BT, 128>>>(x, Wb, bb, Wgk, bgk, A_log, dtb);
    conv_silu<<<dim3(TLEN / 4, 3, 2), 128>>>(cqw, cqb, ckw, ckb, cvw, cvb);
    rope_l2norm<<<2048, 256>>>();
    c1_prep<<<(BT * NH + 7) / 8, 256>>>();
    scan_kernel<<<dim3(16, 8), 128>>>();
    postproc<<<2048, 256>>>(D, onw);
    gemm_out_k<<<dim3(4, 16, 2), 256>>>(Wo);
    add_out<<<(BT * KDIM / 4 + 255) / 256, 256>>>(out);
}